// round 5
// baseline (speedup 1.0000x reference)
#include <cuda_runtime.h>

#define BLK   256
#define ITEMS 2
#define ROWS  (BLK * ITEMS)     // gaussians per block
#define EPS   1e-8f

__global__ __launch_bounds__(BLK) void rssr_kernel(
    const float4* __restrict__ quat,   // N x 4 as float4
    const float*  __restrict__ scale,  // N x 3
    float*        __restrict__ out,    // N x 9
    int N)
{
    __shared__ float s_out[ROWS * 9];  // 18 KB

    const int bbase = blockIdx.x * ROWS;
    const int tid   = threadIdx.x;

    // ---- issue ALL global loads up front (MLP ~ 8 per thread) ----
    float4 qv[ITEMS];
    float  sc[ITEMS][3];
    int    n[ITEMS];
    #pragma unroll
    for (int it = 0; it < ITEMS; it++) {
        n[it] = bbase + it * BLK + tid;
        if (n[it] < N) {
            qv[it] = quat[n[it]];
            // stride-12B per lane: warp spans contiguous 384B -> fully coalesced
            sc[it][0] = scale[n[it] * 3 + 0];
            sc[it][1] = scale[n[it] * 3 + 1];
            sc[it][2] = scale[n[it] * 3 + 2];
        }
    }

    #pragma unroll
    for (int it = 0; it < ITEMS; it++) {
        if (n[it] < N) {
            float w = qv[it].x, x = qv[it].y, y = qv[it].z, z = qv[it].w;
            float inv = rsqrtf(w * w + x * x + y * y + z * z);
            w *= inv; x *= inv; y *= inv; z *= inv;

            float r00 = 1.0f - 2.0f * (y * y + z * z);
            float r01 = 2.0f * (x * y - w * z);
            float r02 = 2.0f * (x * z + w * y);
            float r10 = 2.0f * (x * y + w * z);
            float r11 = 1.0f - 2.0f * (x * x + z * z);
            float r12 = 2.0f * (y * z - w * x);
            float r20 = 2.0f * (x * z - w * y);
            float r21 = 2.0f * (y * z + w * x);
            float r22 = 1.0f - 2.0f * (x * x + y * y);

            float s0 = fabsf(sc[it][0]) + EPS; s0 *= s0;
            float s1 = fabsf(sc[it][1]) + EPS; s1 *= s1;
            float s2 = fabsf(sc[it][2]) + EPS; s2 *= s2;

            float m00 = r00 * r00 * s0 + r01 * r01 * s1 + r02 * r02 * s2;
            float m01 = r00 * r10 * s0 + r01 * r11 * s1 + r02 * r12 * s2;
            float m02 = r00 * r20 * s0 + r01 * r21 * s1 + r02 * r22 * s2;
            float m11 = r10 * r10 * s0 + r11 * r11 * s1 + r12 * r12 * s2;
            float m12 = r10 * r20 * s0 + r11 * r21 * s1 + r12 * r22 * s2;
            float m22 = r20 * r20 * s0 + r21 * r21 * s1 + r22 * r22 * s2;

            // stride-9 smem writes: gcd(9,32)=1 -> conflict-free
            float* o = &s_out[(it * BLK + tid) * 9];
            o[0] = m00; o[1] = m01; o[2] = m02;
            o[3] = m01; o[4] = m11; o[5] = m12;
            o[6] = m02; o[7] = m12; o[8] = m22;
        }
    }
    __syncthreads();

    // ---- flush to global as contiguous streaming float4 stores ----
    const int rows_here = min(ROWS, N - bbase);
    const int cnt = rows_here * 9;
    if (cnt == ROWS * 9) {
        // base byte offset bbase*36: ROWS*36 = 18432, multiple of 16 -> aligned
        float4* out4 = reinterpret_cast<float4*>(out + (size_t)bbase * 9);
        const float4* s4 = reinterpret_cast<const float4*>(s_out);
        #pragma unroll
        for (int i = tid; i < ROWS * 9 / 4; i += BLK) {
            __stcs(&out4[i], s4[i]);   // streaming: output never re-read
        }
    } else {
        float* ob = out + (size_t)bbase * 9;
        for (int i = tid; i < cnt; i += BLK) {
            ob[i] = s_out[i];
        }
    }
}

extern "C" void kernel_launch(void* const* d_in, const int* in_sizes, int n_in,
                              void* d_out, int out_size)
{
    const float4* quat  = (const float4*)d_in[0];  // quaternion (N,4)
    const float*  scale = (const float*)d_in[1];   // scale (N,3)
    float* out = (float*)d_out;                    // (N,3,3)
    int N = in_sizes[0] / 4;
    int grid = (N + ROWS - 1) / ROWS;
    rssr_kernel<<<grid, BLK>>>(quat, scale, out, N);
}